// round 8
// baseline (speedup 1.0000x reference)
#include <cuda_runtime.h>
#include <cuda_bf16.h>
#include <cstdint>

#define NTOK 16384
#define DMODEL 2048
#define NGRP 8
#define HDG 256
#define DH 512   // k * hdg
#define TOKPB 8  // tokens per gate block
#define NQ 4     // pipeline quarters

// ---------------- scratch (no allocs allowed) ----------------
__device__ __align__(16) __nv_bfloat16 g_hin[(size_t)NTOK * DH];   // 16 MB gathered, gated inputs
__device__ __align__(16) __nv_bfloat16 g_wm[(size_t)DH * DH];      // 512 KB bf16 weights ([k][n])
__device__ int g_idx[NTOK * 2];                                    // top-2 group indices per token

extern __shared__ __align__(16) unsigned char dynsmem[];

// ---------------- kernel 1: gate + selective passthrough + gather (+Wm convert) ------------
// 8 tokens/block, 512 threads. Thread owns ONE gate group (tid&7) and 32
// x-elements (s=tid>>3): reduce needs only 2 shuffles/warp/token.
__global__ __launch_bounds__(512, 2) void gate_kernel(const float* __restrict__ x,
                                                      const float* __restrict__ Wg,
                                                      const float* __restrict__ Wm,
                                                      float* __restrict__ out,
                                                      int bid_off) {
    float* xs = (float*)dynsmem;                      // [TOKPB][DMODEL] fp32
    __shared__ float wsum[TOKPB][16][NGRP];
    __shared__ float sG[TOKPB][2];
    __shared__ int   sI[TOKPB][2];

    const int bid  = blockIdx.x + bid_off;
    const int tid  = threadIdx.x;
    const int lane = tid & 31;
    const int warp = tid >> 5;
    const int g    = tid & 7;    // this thread's gate group
    const int s    = tid >> 3;   // element-slice index, 0..63
    const size_t tok0 = (size_t)bid * TOKPB;

    // stage 8 token rows via cp.async in two 32KB halves (tokens 0-3, 4-7)
    const uint32_t sx = (uint32_t)__cvta_generic_to_shared(xs);
    const float* src0 = x + tok0 * DMODEL;
#pragma unroll
    for (int i = 0; i < 4; i++) {
        int q = tid + i * 512;
        asm volatile("cp.async.cg.shared.global [%0], [%1], 16;\n"
                     :: "r"(sx + q * 16), "l"(src0 + q * 4));
    }
    asm volatile("cp.async.commit_group;\n");
#pragma unroll
    for (int i = 0; i < 4; i++) {
        int q = 2048 + tid + i * 512;
        asm volatile("cp.async.cg.shared.global [%0], [%1], 16;\n"
                     :: "r"(sx + q * 16), "l"(src0 + q * 4));
    }
    asm volatile("cp.async.commit_group;\n");

    // folded Wm fp32 -> bf16 conversion (quarter 0 blocks 0..511 cover all of Wm)
    if (bid < 512) {
        int i = bid * 512 + tid;
        g_wm[i] = __float2bfloat16(Wm[i]);
    }

    // Wg column-slice register cache: Wg[e][g] for e = k*256 + s*4 + c  (32 regs)
    float wgc[32];
#pragma unroll
    for (int k = 0; k < 8; k++)
#pragma unroll
        for (int c = 0; c < 4; c++)
            wgc[k * 4 + c] = __ldg(Wg + (size_t)(k * 256 + s * 4 + c) * NGRP + g);

    // first half arrived -> logits for tokens 0-3 while 4-7 still loading
    asm volatile("cp.async.wait_group 1;\n");
    __syncthreads();

#pragma unroll 2
    for (int t = 0; t < TOKPB / 2; t++) {
        const float4* xt = (const float4*)(xs + t * DMODEL);
        float a0 = 0.f, a1 = 0.f, a2 = 0.f, a3 = 0.f;
#pragma unroll
        for (int k = 0; k < 8; k++) {
            float4 v = xt[k * 64 + s];           // broadcast across 8 same-s lanes
            a0 += v.x * wgc[k * 4 + 0];
            a1 += v.y * wgc[k * 4 + 1];
            a2 += v.z * wgc[k * 4 + 2];
            a3 += v.w * wgc[k * 4 + 3];
        }
        float p = (a0 + a1) + (a2 + a3);
        p += __shfl_xor_sync(0xffffffffu, p, 8);
        p += __shfl_xor_sync(0xffffffffu, p, 16);
        if (lane < NGRP) wsum[t][warp][lane] = p;   // lane==g for lane<8
    }

    asm volatile("cp.async.wait_group 0;\n");
    __syncthreads();

#pragma unroll 2
    for (int t = TOKPB / 2; t < TOKPB; t++) {
        const float4* xt = (const float4*)(xs + t * DMODEL);
        float a0 = 0.f, a1 = 0.f, a2 = 0.f, a3 = 0.f;
#pragma unroll
        for (int k = 0; k < 8; k++) {
            float4 v = xt[k * 64 + s];
            a0 += v.x * wgc[k * 4 + 0];
            a1 += v.y * wgc[k * 4 + 1];
            a2 += v.z * wgc[k * 4 + 2];
            a3 += v.w * wgc[k * 4 + 3];
        }
        float p = (a0 + a1) + (a2 + a3);
        p += __shfl_xor_sync(0xffffffffu, p, 8);
        p += __shfl_xor_sync(0xffffffffu, p, 16);
        if (lane < NGRP) wsum[t][warp][lane] = p;
    }
    __syncthreads();

    // softmax + top-2, one token per lane
    if (tid < TOKPB) {
        int t = tid;
        float l[NGRP];
#pragma unroll
        for (int j = 0; j < NGRP; j++) {
            float sum = 0.f;
#pragma unroll
            for (int w = 0; w < 16; w++) sum += wsum[t][w][j];
            l[j] = sum;
        }
        float m = l[0];
#pragma unroll
        for (int j = 1; j < NGRP; j++) m = fmaxf(m, l[j]);
        float e[NGRP], ssum = 0.f;
#pragma unroll
        for (int j = 0; j < NGRP; j++) { e[j] = expf(l[j] - m); ssum += e[j]; }
        int i0 = 0;
#pragma unroll
        for (int j = 1; j < NGRP; j++) if (e[j] > e[i0]) i0 = j;
        int i1 = (i0 == 0) ? 1 : 0;
#pragma unroll
        for (int j = 0; j < NGRP; j++) if (j != i0 && e[j] > e[i1]) i1 = j;
        float inv = 1.f / ssum;
        sG[t][0] = e[i0] * inv;  sG[t][1] = e[i1] * inv;
        sI[t][0] = i0;           sI[t][1] = i1;
        g_idx[(tok0 + t) * 2 + 0] = i0;
        g_idx[(tok0 + t) * 2 + 1] = i1;
    }
    __syncthreads();

    // passthrough (skip selected groups; GEMM writes those): 1 chunk/thread/token
#pragma unroll 1
    for (int t = 0; t < TOKPB; t++) {
        int i0 = sI[t][0], i1 = sI[t][1];
        int grp = tid >> 6;
        if (grp != i0 && grp != i1) {
            float4* orow = (float4*)(out + (tok0 + t) * DMODEL);
            __stcs(&orow[tid], ((const float4*)(xs + t * DMODEL))[tid]);
        }
    }
    // gather + gate -> g_hin: 2 tokens per pass, 256 threads each
#pragma unroll
    for (int it = 0; it < 4; it++) {
        int tloc = it * 2 + (tid >> 8);
        int p    = tid & 255;
        int half = p >> 7;
        float gate = sG[tloc][half];
        int base2 = sI[tloc][half] * (HDG / 2) + (p & 127);
        float2 xv = ((const float2*)(xs + tloc * DMODEL))[base2];
        ((__nv_bfloat162*)g_hin)[(tok0 + tloc) * (DH / 2) + p] =
            __floats2bfloat162_rn(gate * xv.x, gate * xv.y);
    }
}

// ---------------- kernel 2: GEMM [M,512]x[512,512] bf16 -> fp32, scatter epilogue ----------
// BM=128, BN=64, BK=64, 256 threads, 3-stage cp.async pipeline, 72KB dynamic smem.
// (R3/R5/R6 configuration: measured 29.5-30.1us full-size)
#define BM 128
#define BN 64
#define BK 64
#define STAGE_BYTES (BM * BK * 2 + BK * BN * 2)   // 16KB + 8KB = 24KB

__device__ __forceinline__ uint32_t sw_off(uint32_t row, uint32_t g) {
    return row * 128u + ((g ^ (row & 7u)) * 16u);
}

__global__ __launch_bounds__(256) void gemm_scatter(const float* __restrict__ bias,
                                                    float* __restrict__ out,
                                                    int bm_off) {
    const int tid  = threadIdx.x;
    const int lane = tid & 31;
    const int warp = tid >> 5;
    const int wm   = warp >> 1;
    const int wn   = warp & 1;
    const int bn   = blockIdx.x;             // 0..7
    const int bm   = blockIdx.y + bm_off;    // global M tile

    const __nv_bfloat16* Ag = g_hin + (size_t)(bm * BM) * DH;
    const __nv_bfloat16* Bg = g_wm + (size_t)(bn * BN);

    const uint32_t sBase = (uint32_t)__cvta_generic_to_shared(dynsmem);

    auto load_stage = [&](int s, int kt) {
        uint32_t sA = sBase + s * STAGE_BYTES;
        uint32_t sB = sA + BM * BK * 2;
#pragma unroll
        for (int i = 0; i < 4; i++) {
            int q = tid + i * 256;
            int r = q >> 3, g = q & 7;
            const __nv_bfloat16* src = Ag + (size_t)r * DH + kt + g * 8;
            asm volatile("cp.async.cg.shared.global [%0], [%1], 16;\n"
                         :: "r"(sA + sw_off(r, g)), "l"(src));
        }
#pragma unroll
        for (int i = 0; i < 2; i++) {
            int q = tid + i * 256;
            int r = q >> 3, g = q & 7;
            const __nv_bfloat16* src = Bg + (size_t)(kt + r) * DH + g * 8;
            asm volatile("cp.async.cg.shared.global [%0], [%1], 16;\n"
                         :: "r"(sB + sw_off(r, g)), "l"(src));
        }
        asm volatile("cp.async.commit_group;\n");
    };

    float acc[2][4][4];
#pragma unroll
    for (int a = 0; a < 2; a++)
#pragma unroll
        for (int b = 0; b < 4; b++)
#pragma unroll
            for (int c = 0; c < 4; c++) acc[a][b][c] = 0.f;

    const int NKT = DH / BK;   // 8
    load_stage(0, 0);
    load_stage(1, BK);

    for (int k = 0; k < NKT; k++) {
        if (k < NKT - 1) asm volatile("cp.async.wait_group 1;\n");
        else             asm volatile("cp.async.wait_group 0;\n");
        __syncthreads();

        if (k + 2 < NKT) load_stage((k + 2) % 3, (k + 2) * BK);

        uint32_t sA = sBase + (k % 3) * STAGE_BYTES;
        uint32_t sB = sA + BM * BK * 2;
#pragma unroll
        for (int ks = 0; ks < 4; ks++) {
            uint32_t a[2][4];
#pragma unroll
            for (int mt = 0; mt < 2; mt++) {
                uint32_t row = wm * 32 + mt * 16 + (lane & 15);
                uint32_t gg  = ks * 2 + (lane >> 4);
                uint32_t addr = sA + sw_off(row, gg);
                asm volatile(
                    "ldmatrix.sync.aligned.m8n8.x4.shared.b16 {%0,%1,%2,%3}, [%4];"
                    : "=r"(a[mt][0]), "=r"(a[mt][1]), "=r"(a[mt][2]), "=r"(a[mt][3])
                    : "r"(addr));
            }
            uint32_t b[4][2];
#pragma unroll
            for (int half = 0; half < 2; half++) {
                uint32_t row = ks * 16 + (lane & 15);
                uint32_t gg  = wn * 4 + half * 2 + (lane >> 4);
                uint32_t addr = sB + sw_off(row, gg);
                uint32_t r0, r1, r2, r3;
                asm volatile(
                    "ldmatrix.sync.aligned.m8n8.x4.trans.shared.b16 {%0,%1,%2,%3}, [%4];"
                    : "=r"(r0), "=r"(r1), "=r"(r2), "=r"(r3)
                    : "r"(addr));
                b[half * 2 + 0][0] = r0; b[half * 2 + 0][1] = r1;
                b[half * 2 + 1][0] = r2; b[half * 2 + 1][1] = r3;
            }
#pragma unroll
            for (int mt = 0; mt < 2; mt++)
#pragma unroll
                for (int nt = 0; nt < 4; nt++) {
                    asm volatile(
                        "mma.sync.aligned.m16n8k16.row.col.f32.bf16.bf16.f32 "
                        "{%0,%1,%2,%3}, {%4,%5,%6,%7}, {%8,%9}, {%0,%1,%2,%3};"
                        : "+f"(acc[mt][nt][0]), "+f"(acc[mt][nt][1]),
                          "+f"(acc[mt][nt][2]), "+f"(acc[mt][nt][3])
                        : "r"(a[mt][0]), "r"(a[mt][1]), "r"(a[mt][2]), "r"(a[mt][3]),
                          "r"(b[nt][0]), "r"(b[nt][1]));
                }
        }
    }

    const int gsel = bn >> 2;
#pragma unroll
    for (int mt = 0; mt < 2; mt++) {
#pragma unroll
        for (int rr = 0; rr < 2; rr++) {
            int tok = bm * BM + wm * 32 + mt * 16 + (lane >> 2) + rr * 8;
            int grp = g_idx[tok * 2 + gsel];
            float* orow = out + (size_t)tok * DMODEL + grp * HDG;
#pragma unroll
            for (int nt = 0; nt < 4; nt++) {
                int c  = bn * BN + wn * 32 + nt * 8 + (lane & 3) * 2;
                int cl = c & (HDG - 1);
                float2 bv = *(const float2*)(bias + c);
                float2 v;
                v.x = acc[mt][nt][rr * 2 + 0] + bv.x;
                v.y = acc[mt][nt][rr * 2 + 1] + bv.y;
                *(float2*)(orow + cl) = v;
            }
        }
    }
}

// ---------------- launch: 4-quarter gate/GEMM pipeline across two streams ----------------
extern "C" void kernel_launch(void* const* d_in, const int* in_sizes, int n_in,
                              void* d_out, int out_size) {
    const float* x    = (const float*)d_in[0];
    const float* Wg   = (const float*)d_in[1];
    const float* Wm   = (const float*)d_in[2];
    const float* bias = (const float*)d_in[3];
    float* out = (float*)d_out;

    static cudaStream_t s1 = nullptr;
    static cudaEvent_t evGate[NQ];
    static cudaEvent_t evDone = nullptr;
    if (s1 == nullptr) {
        cudaFuncSetAttribute(gate_kernel,
                             cudaFuncAttributeMaxDynamicSharedMemorySize, TOKPB * DMODEL * 4);
        cudaFuncSetAttribute(gemm_scatter,
                             cudaFuncAttributeMaxDynamicSharedMemorySize, 3 * STAGE_BYTES);
        cudaStreamCreateWithFlags(&s1, cudaStreamNonBlocking);
        for (int q = 0; q < NQ; q++)
            cudaEventCreateWithFlags(&evGate[q], cudaEventDisableTiming);
        cudaEventCreateWithFlags(&evDone, cudaEventDisableTiming);
    }

    const int gateBlkQ = (NTOK / TOKPB) / NQ;   // 512 gate blocks per quarter
    const int bmQ      = (NTOK / BM) / NQ;      // 32 M-tiles per quarter

    for (int q = 0; q < NQ; q++) {
        gate_kernel<<<gateBlkQ, 512, TOKPB * DMODEL * 4>>>(x, Wg, Wm, out, q * gateBlkQ);
        cudaEventRecord(evGate[q], 0);
        cudaStreamWaitEvent(s1, evGate[q], 0);
        dim3 grid(DH / BN, bmQ);
        gemm_scatter<<<grid, 256, 3 * STAGE_BYTES, s1>>>(bias, out, q * bmQ);
    }
    cudaEventRecord(evDone, s1);
    cudaStreamWaitEvent(0, evDone, 0);
}

// round 9
// speedup vs baseline: 1.0410x; 1.0410x over previous
#include <cuda_runtime.h>
#include <cuda_bf16.h>
#include <cstdint>

#define NTOK 16384
#define DMODEL 2048
#define NGRP 8
#define HDG 256
#define DH 512        // k * hdg
#define BMF 128       // tokens per fused block
#define NBATCH 32     // 4-token gate batches per block

// ---------------- scratch (no allocs allowed) ----------------
__device__ __align__(16) __nv_bfloat16 g_wm[(size_t)DH * DH];   // 512 KB bf16 weights [k][n]

extern __shared__ __align__(16) unsigned char dynsmem[];

// smem layout (dynamic, 192KB):
//   [0, 128K)        A tiles: 8 x [128 rows x 64 cols bf16], swizzled (16KB each)
//   [128K, 192K)     union: gate x-buffers (2 x 32KB) / GEMM B buffers (2 x 32KB)
#define SM_A 0
#define SM_X (128 * 1024)
#define FUSED_SMEM (192 * 1024)

// ---------------- kernel 0: Wm fp32 -> bf16 ----------------
__global__ void convert_wm(const float* __restrict__ Wm) {
    int i = blockIdx.x * 256 + threadIdx.x;   // 1024*256 == 262144
    g_wm[i] = __float2bfloat16(Wm[i]);
}

// A tile swizzle: [128 rows x 64 cols bf16], 128B rows, 16B-granule XOR
__device__ __forceinline__ uint32_t swA(uint32_t row, uint32_t g) {
    return row * 128u + ((g ^ (row & 7u)) * 16u);
}
// B tile swizzle: [64 rows x 256 cols bf16], 512B rows, XOR within 128B halves
__device__ __forceinline__ uint32_t swB(uint32_t row, uint32_t g) {
    return row * 512u + (((g & 24u) | ((g ^ row) & 7u)) * 16u);
}

// ---------------- fused kernel: gate + gather + GEMM + scatter ----------------
__global__ __launch_bounds__(512, 1) void mof_fused(const float* __restrict__ x,
                                                    const float* __restrict__ Wg,
                                                    const float* __restrict__ bias,
                                                    float* __restrict__ out) {
    __shared__ float wsum[4][16][NGRP];
    __shared__ float sG[4][2];
    __shared__ int   sI[4][2];
    __shared__ int   sIdx[BMF][2];

    const int tid  = threadIdx.x;
    const int lane = tid & 31;
    const int warp = tid >> 5;
    const size_t tok0 = (size_t)blockIdx.x * BMF;

    const uint32_t sbase = (uint32_t)__cvta_generic_to_shared(dynsmem);
    const uint32_t sA = sbase + SM_A;
    const uint32_t sX = sbase + SM_X;
    float* xsm = (float*)(dynsmem + SM_X);

    // ===================== PHASE 1: gate + gather =====================
    const int g = tid & 7;     // gate group owned by this thread
    const int s = tid >> 3;    // element slice 0..63

    // Wg column-slice register cache (32 regs)
    float wgc[32];
#pragma unroll
    for (int k = 0; k < 8; k++)
#pragma unroll
        for (int c = 0; c < 4; c++)
            wgc[k * 4 + c] = __ldg(Wg + (size_t)(k * 256 + s * 4 + c) * NGRP + g);

    // prefetch batches 0,1 (4 tokens = 32KB each)
    auto load_batch = [&](int b) {
        uint32_t dst = sX + (b & 1) * 32768;
        const float* src = x + (tok0 + b * 4) * DMODEL;
#pragma unroll
        for (int i = 0; i < 4; i++) {
            int q = tid + i * 512;           // 2048 16B chunks
            asm volatile("cp.async.cg.shared.global [%0], [%1], 16;\n"
                         :: "r"(dst + q * 16), "l"(src + q * 4));
        }
        asm volatile("cp.async.commit_group;\n");
    };
    load_batch(0);
    load_batch(1);

#pragma unroll 1
    for (int b = 0; b < NBATCH; b++) {
        if (b < NBATCH - 1) asm volatile("cp.async.wait_group 1;\n");
        else                asm volatile("cp.async.wait_group 0;\n");
        __syncthreads();

        const float* xb = xsm + (b & 1) * 8192;

        // logits for 4 tokens
#pragma unroll
        for (int t = 0; t < 4; t++) {
            const float4* xt = (const float4*)(xb + t * DMODEL);
            float a0 = 0.f, a1 = 0.f, a2 = 0.f, a3 = 0.f;
#pragma unroll
            for (int k = 0; k < 8; k++) {
                float4 v = xt[k * 64 + s];
                a0 += v.x * wgc[k * 4 + 0];
                a1 += v.y * wgc[k * 4 + 1];
                a2 += v.z * wgc[k * 4 + 2];
                a3 += v.w * wgc[k * 4 + 3];
            }
            float p = (a0 + a1) + (a2 + a3);
            p += __shfl_xor_sync(0xffffffffu, p, 8);
            p += __shfl_xor_sync(0xffffffffu, p, 16);
            if (lane < NGRP) wsum[t][warp][lane] = p;
        }
        __syncthreads();

        // softmax + top-2: one token per lane (tid<4)
        if (tid < 4) {
            int t = tid;
            float l[NGRP];
#pragma unroll
            for (int j = 0; j < NGRP; j++) {
                float sum = 0.f;
#pragma unroll
                for (int w = 0; w < 16; w++) sum += wsum[t][w][j];
                l[j] = sum;
            }
            float m = l[0];
#pragma unroll
            for (int j = 1; j < NGRP; j++) m = fmaxf(m, l[j]);
            float e[NGRP], ssum = 0.f;
#pragma unroll
            for (int j = 0; j < NGRP; j++) { e[j] = expf(l[j] - m); ssum += e[j]; }
            int i0 = 0;
#pragma unroll
            for (int j = 1; j < NGRP; j++) if (e[j] > e[i0]) i0 = j;
            int i1 = (i0 == 0) ? 1 : 0;
#pragma unroll
            for (int j = 0; j < NGRP; j++) if (j != i0 && e[j] > e[i1]) i1 = j;
            float inv = 1.f / ssum;
            sG[t][0] = e[i0] * inv;  sG[t][1] = e[i1] * inv;
            sI[t][0] = i0;           sI[t][1] = i1;
            sIdx[b * 4 + t][0] = i0;
            sIdx[b * 4 + t][1] = i1;
        }
        __syncthreads();

        // passthrough (skip selected groups) : 1 float4 chunk/thread/token
#pragma unroll
        for (int t = 0; t < 4; t++) {
            int i0 = sI[t][0], i1 = sI[t][1];
            int grp = tid >> 6;
            if (grp != i0 && grp != i1) {
                float4* orow = (float4*)(out + (tok0 + b * 4 + t) * DMODEL);
                __stcs(&orow[tid], ((const float4*)(xb + t * DMODEL))[tid]);
            }
        }
        // gather + gate -> A tiles in smem (bf16x2 per thread, 2 tokens/iter)
#pragma unroll
        for (int it = 0; it < 2; it++) {
            int tloc = it * 2 + (tid >> 8);          // 0..3
            int p    = tid & 255;                    // pair index: cols 2p,2p+1
            int half = p >> 7;
            float gate = sG[tloc][half];
            int base2 = sI[tloc][half] * (HDG / 2) + (p & 127);
            float2 xv = ((const float2*)(xb + tloc * DMODEL))[base2];
            uint32_t hv;
            {
                __nv_bfloat162 t2 = __floats2bfloat162_rn(gate * xv.x, gate * xv.y);
                hv = *(uint32_t*)&t2;
            }
            uint32_t row = b * 4 + tloc;
            uint32_t col = p * 2;
            uint32_t kt  = col >> 6;
            uint32_t c   = col & 63;
            uint32_t addr = sA + kt * 16384 + swA(row, c >> 3) + (c & 7) * 2;
            asm volatile("st.shared.u32 [%0], %1;\n" :: "r"(addr), "r"(hv));
        }
        __syncthreads();

        if (b + 2 < NBATCH) load_batch(b + 2);
    }

    // ===================== PHASE 2: GEMM + scatter =====================
    // A resident in smem (8 k-tiles). N in 2 chunks of 256. 16 warps: 4(M) x 4(N),
    // warp tile 32 x 64. B double-buffered in the X region (2 x 32KB).
    const int wm = warp >> 2;   // 0..3 -> 32 M rows
    const int wn = warp & 3;    // 0..3 -> 64 N cols

    auto load_B = [&](int buf, int kt, int nb) {
        uint32_t dst = sX + buf * 32768;
        const __nv_bfloat16* src0 = g_wm + (size_t)(kt * 64) * DH + nb * 256;
#pragma unroll
        for (int i = 0; i < 4; i++) {
            int q = tid + i * 512;               // 2048 16B chunks
            int r = q >> 5, gg = q & 31;
            asm volatile("cp.async.cg.shared.global [%0], [%1], 16;\n"
                         :: "r"(dst + swB(r, gg)), "l"(src0 + (size_t)r * DH + gg * 8));
        }
        asm volatile("cp.async.commit_group;\n");
    };

#pragma unroll 1
    for (int nb = 0; nb < 2; nb++) {
        __syncthreads();
        load_B(0, 0, nb);
        load_B(1, 1, nb);

        float acc[2][8][4];
#pragma unroll
        for (int a = 0; a < 2; a++)
#pragma unroll
            for (int bb = 0; bb < 8; bb++)
#pragma unroll
                for (int c = 0; c < 4; c++) acc[a][bb][c] = 0.f;

#pragma unroll 1
        for (int kt = 0; kt < 8; kt++) {
            if (kt < 7) asm volatile("cp.async.wait_group 1;\n");
            else        asm volatile("cp.async.wait_group 0;\n");
            __syncthreads();

            uint32_t sAk = sA + kt * 16384;
            uint32_t sB  = sX + (kt & 1) * 32768;
#pragma unroll
            for (int ks = 0; ks < 4; ks++) {
                uint32_t a[2][4];
#pragma unroll
                for (int mt = 0; mt < 2; mt++) {
                    uint32_t row = wm * 32 + mt * 16 + (lane & 15);
                    uint32_t gg  = ks * 2 + (lane >> 4);
                    uint32_t addr = sAk + swA(row, gg);
                    asm volatile(
                        "ldmatrix.sync.aligned.m8n8.x4.shared.b16 {%0,%1,%2,%3}, [%4];"
                        : "=r"(a[mt][0]), "=r"(a[mt][1]), "=r"(a[mt][2]), "=r"(a[mt][3])
                        : "r"(addr));
                }
                uint32_t bfr[8][2];
#pragma unroll
                for (int q4 = 0; q4 < 4; q4++) {
                    uint32_t row = ks * 16 + (lane & 15);
                    uint32_t gg  = wn * 8 + q4 * 2 + (lane >> 4);
                    uint32_t addr = sB + swB(row, gg);
                    uint32_t r0, r1, r2, r3;
                    asm volatile(
                        "ldmatrix.sync.aligned.m8n8.x4.trans.shared.b16 {%0,%1,%2,%3}, [%4];"
                        : "=r"(r0), "=r"(r1), "=r"(r2), "=r"(r3)
                        : "r"(addr));
                    bfr[q4 * 2 + 0][0] = r0; bfr[q4 * 2 + 0][1] = r1;
                    bfr[q4 * 2 + 1][0] = r2; bfr[q4 * 2 + 1][1] = r3;
                }
#pragma unroll
                for (int mt = 0; mt < 2; mt++)
#pragma unroll
                    for (int nt = 0; nt < 8; nt++) {
                        asm volatile(
                            "mma.sync.aligned.m16n8k16.row.col.f32.bf16.bf16.f32 "
                            "{%0,%1,%2,%3}, {%4,%5,%6,%7}, {%8,%9}, {%0,%1,%2,%3};"
                            : "+f"(acc[mt][nt][0]), "+f"(acc[mt][nt][1]),
                              "+f"(acc[mt][nt][2]), "+f"(acc[mt][nt][3])
                            : "r"(a[mt][0]), "r"(a[mt][1]), "r"(a[mt][2]), "r"(a[mt][3]),
                              "r"(bfr[nt][0]), "r"(bfr[nt][1]));
                    }
            }
            __syncthreads();
            if (kt + 2 < 8) load_B(kt & 1, kt + 2, nb);
        }

        // epilogue: bias + scatter into selected group
#pragma unroll
        for (int mt = 0; mt < 2; mt++) {
#pragma unroll
            for (int rr = 0; rr < 2; rr++) {
                int tl  = wm * 32 + mt * 16 + (lane >> 2) + rr * 8;
                size_t tokg = tok0 + tl;
#pragma unroll
                for (int nt = 0; nt < 8; nt++) {
                    int c    = nb * 256 + wn * 64 + nt * 8 + (lane & 3) * 2;
                    int gsel = c >> 8;
                    int cl   = c & (HDG - 1);
                    int grp  = sIdx[tl][gsel];
                    float2 bv = *(const float2*)(bias + c);
                    float2 v;
                    v.x = acc[mt][nt][rr * 2 + 0] + bv.x;
                    v.y = acc[mt][nt][rr * 2 + 1] + bv.y;
                    *(float2*)(out + tokg * DMODEL + grp * HDG + cl) = v;
                }
            }
        }
    }
}

// ---------------- launch ----------------
extern "C" void kernel_launch(void* const* d_in, const int* in_sizes, int n_in,
                              void* d_out, int out_size) {
    const float* x    = (const float*)d_in[0];
    const float* Wg   = (const float*)d_in[1];
    const float* Wm   = (const float*)d_in[2];
    const float* bias = (const float*)d_in[3];
    float* out = (float*)d_out;

    static bool attr_done = false;
    if (!attr_done) {
        cudaFuncSetAttribute(mof_fused,
                             cudaFuncAttributeMaxDynamicSharedMemorySize, FUSED_SMEM);
        attr_done = true;
    }

    convert_wm<<<1024, 256>>>(Wm);
    mof_fused<<<NTOK / BMF, 512, FUSED_SMEM>>>(x, Wg, bias, out);
}

// round 10
// speedup vs baseline: 1.0970x; 1.0538x over previous
#include <cuda_runtime.h>
#include <cuda_bf16.h>
#include <cstdint>

#define NTOK 16384
#define DMODEL 2048
#define NGRP 8
#define HDG 256
#define DH 512   // k * hdg
#define TOKPB 8  // tokens per gate block

// ---------------- scratch (no allocs allowed) ----------------
__device__ __align__(16) __nv_bfloat16 g_hin[(size_t)NTOK * DH];   // 16 MB gathered, gated inputs
__device__ __align__(16) __nv_bfloat16 g_wm[(size_t)DH * DH];      // 512 KB bf16 weights ([k][n])
__device__ int g_idx[NTOK * 2];                                    // top-2 group indices per token

extern __shared__ __align__(16) unsigned char dynsmem[];

// ---------------- kernel 1: gate + selective passthrough + gather (+Wm convert) ------------
// 8 tokens/block, 512 threads. Thread owns TWO gate groups {gsel, gsel+4}
// (gsel = tid&3) and 16 x-elements (s = tid>>2): logit smem reads are halved
// vs one-group ownership, at 5 shuffles/token.
__global__ __launch_bounds__(512, 2) void gate_kernel(const float* __restrict__ x,
                                                      const float* __restrict__ Wg,
                                                      const float* __restrict__ Wm,
                                                      float* __restrict__ out) {
    float* xs = (float*)dynsmem;                      // [TOKPB][DMODEL] fp32
    __shared__ float wsum[TOKPB][16][NGRP];
    __shared__ float sG[TOKPB][2];
    __shared__ int   sI[TOKPB][2];

    const int tid  = threadIdx.x;
    const int lane = tid & 31;
    const int warp = tid >> 5;
    const int gsel = tid & 3;    // owns groups gsel and gsel+4
    const int s    = tid >> 2;   // element-slice index, 0..127 (16 elems each)
    const size_t tok0 = (size_t)blockIdx.x * TOKPB;

    // stage 8 token rows via cp.async in two 32KB halves (tokens 0-3, 4-7)
    const uint32_t sx = (uint32_t)__cvta_generic_to_shared(xs);
    const float* src0 = x + tok0 * DMODEL;
#pragma unroll
    for (int i = 0; i < 4; i++) {
        int q = tid + i * 512;
        asm volatile("cp.async.cg.shared.global [%0], [%1], 16;\n"
                     :: "r"(sx + q * 16), "l"(src0 + q * 4));
    }
    asm volatile("cp.async.commit_group;\n");
#pragma unroll
    for (int i = 0; i < 4; i++) {
        int q = 2048 + tid + i * 512;
        asm volatile("cp.async.cg.shared.global [%0], [%1], 16;\n"
                     :: "r"(sx + q * 16), "l"(src0 + q * 4));
    }
    asm volatile("cp.async.commit_group;\n");

    // folded Wm fp32 -> bf16 conversion (blocks 0..511 cover all of Wm)
    if (blockIdx.x < 512) {
        int i = blockIdx.x * 512 + tid;
        g_wm[i] = __float2bfloat16(Wm[i]);
    }

    // Wg 2-column register cache: wgc[8q + 2i + h] = Wg[s*16 + q*4 + i][gsel + 4h]
    float wgc[32];
#pragma unroll
    for (int q = 0; q < 4; q++)
#pragma unroll
        for (int i = 0; i < 4; i++) {
            const float* row = Wg + (size_t)(s * 16 + q * 4 + i) * NGRP;
            wgc[8 * q + 2 * i + 0] = __ldg(row + gsel);
            wgc[8 * q + 2 * i + 1] = __ldg(row + gsel + 4);
        }

    // first half arrived -> logits for tokens 0-3 while 4-7 still loading
    asm volatile("cp.async.wait_group 1;\n");
    __syncthreads();

#pragma unroll 2
    for (int t = 0; t < TOKPB / 2; t++) {
        const float4* xt = (const float4*)(xs + t * DMODEL);
        float p0 = 0.f, p1 = 0.f;
#pragma unroll
        for (int q = 0; q < 4; q++) {
            float4 v = xt[s * 4 + q];
            p0 += v.x * wgc[8 * q + 0];  p1 += v.x * wgc[8 * q + 1];
            p0 += v.y * wgc[8 * q + 2];  p1 += v.y * wgc[8 * q + 3];
            p0 += v.z * wgc[8 * q + 4];  p1 += v.z * wgc[8 * q + 5];
            p0 += v.w * wgc[8 * q + 6];  p1 += v.w * wgc[8 * q + 7];
        }
        p0 += __shfl_xor_sync(0xffffffffu, p0, 4);
        p1 += __shfl_xor_sync(0xffffffffu, p1, 4);
        p0 += __shfl_xor_sync(0xffffffffu, p0, 8);
        p1 += __shfl_xor_sync(0xffffffffu, p1, 8);
        float send = (lane & 16) ? p0 : p1;
        float r = __shfl_xor_sync(0xffffffffu, send, 16);
        float res = ((lane & 16) ? p1 : p0) + r;
        // lane<16: res = sum for group gsel; lane>=16: group gsel+4
        if (lane < 4)                       wsum[t][warp][gsel] = res;
        else if (lane >= 16 && lane < 20)   wsum[t][warp][gsel + 4] = res;
    }

    asm volatile("cp.async.wait_group 0;\n");
    __syncthreads();

#pragma unroll 2
    for (int t = TOKPB / 2; t < TOKPB; t++) {
        const float4* xt = (const float4*)(xs + t * DMODEL);
        float p0 = 0.f, p1 = 0.f;
#pragma unroll
        for (int q = 0; q < 4; q++) {
            float4 v = xt[s * 4 + q];
            p0 += v.x * wgc[8 * q + 0];  p1 += v.x * wgc[8 * q + 1];
            p0 += v.y * wgc[8 * q + 2];  p1 += v.y * wgc[8 * q + 3];
            p0 += v.z * wgc[8 * q + 4];  p1 += v.z * wgc[8 * q + 5];
            p0 += v.w * wgc[8 * q + 6];  p1 += v.w * wgc[8 * q + 7];
        }
        p0 += __shfl_xor_sync(0xffffffffu, p0, 4);
        p1 += __shfl_xor_sync(0xffffffffu, p1, 4);
        p0 += __shfl_xor_sync(0xffffffffu, p0, 8);
        p1 += __shfl_xor_sync(0xffffffffu, p1, 8);
        float send = (lane & 16) ? p0 : p1;
        float r = __shfl_xor_sync(0xffffffffu, send, 16);
        float res = ((lane & 16) ? p1 : p0) + r;
        if (lane < 4)                       wsum[t][warp][gsel] = res;
        else if (lane >= 16 && lane < 20)   wsum[t][warp][gsel + 4] = res;
    }
    __syncthreads();

    // softmax + top-2, one token per lane
    if (tid < TOKPB) {
        int t = tid;
        float l[NGRP];
#pragma unroll
        for (int j = 0; j < NGRP; j++) {
            float sum = 0.f;
#pragma unroll
            for (int w = 0; w < 16; w++) sum += wsum[t][w][j];
            l[j] = sum;
        }
        float m = l[0];
#pragma unroll
        for (int j = 1; j < NGRP; j++) m = fmaxf(m, l[j]);
        float e[NGRP], ssum = 0.f;
#pragma unroll
        for (int j = 0; j < NGRP; j++) { e[j] = expf(l[j] - m); ssum += e[j]; }
        int i0 = 0;
#pragma unroll
        for (int j = 1; j < NGRP; j++) if (e[j] > e[i0]) i0 = j;
        int i1 = (i0 == 0) ? 1 : 0;
#pragma unroll
        for (int j = 0; j < NGRP; j++) if (j != i0 && e[j] > e[i1]) i1 = j;
        float inv = 1.f / ssum;
        sG[t][0] = e[i0] * inv;  sG[t][1] = e[i1] * inv;
        sI[t][0] = i0;           sI[t][1] = i1;
        g_idx[(tok0 + t) * 2 + 0] = i0;
        g_idx[(tok0 + t) * 2 + 1] = i1;
    }
    __syncthreads();

    // passthrough (skip selected groups; GEMM writes those): 1 chunk/thread/token
#pragma unroll 1
    for (int t = 0; t < TOKPB; t++) {
        int i0 = sI[t][0], i1 = sI[t][1];
        int grp = tid >> 6;
        if (grp != i0 && grp != i1) {
            float4* orow = (float4*)(out + (tok0 + t) * DMODEL);
            __stcs(&orow[tid], ((const float4*)(xs + t * DMODEL))[tid]);
        }
    }
    // gather + gate -> g_hin: 2 tokens per pass, 256 threads each
#pragma unroll
    for (int it = 0; it < 4; it++) {
        int tloc = it * 2 + (tid >> 8);
        int p    = tid & 255;
        int half = p >> 7;
        float gate = sG[tloc][half];
        int base2 = sI[tloc][half] * (HDG / 2) + (p & 127);
        float2 xv = ((const float2*)(xs + tloc * DMODEL))[base2];
        ((__nv_bfloat162*)g_hin)[(tok0 + tloc) * (DH / 2) + p] =
            __floats2bfloat162_rn(gate * xv.x, gate * xv.y);
    }
}

// ---------------- kernel 2: GEMM [16384,512]x[512,512] bf16 -> fp32, scatter epilogue --------
// BM=128, BN=64, BK=64, 256 threads, 3-stage cp.async pipeline, 72KB dynamic smem.
// (R3/R5/R6 configuration: measured 29.5-30.1us)
#define BM 128
#define BN 64
#define BK 64
#define STAGE_BYTES (BM * BK * 2 + BK * BN * 2)   // 16KB + 8KB = 24KB

__device__ __forceinline__ uint32_t sw_off(uint32_t row, uint32_t g) {
    return row * 128u + ((g ^ (row & 7u)) * 16u);
}

__global__ __launch_bounds__(256) void gemm_scatter(const float* __restrict__ bias,
                                                    float* __restrict__ out) {
    const int tid  = threadIdx.x;
    const int lane = tid & 31;
    const int warp = tid >> 5;
    const int wm   = warp >> 1;
    const int wn   = warp & 1;
    const int bn   = blockIdx.x;  // 0..7
    const int bm   = blockIdx.y;  // 0..127

    const __nv_bfloat16* Ag = g_hin + (size_t)(bm * BM) * DH;
    const __nv_bfloat16* Bg = g_wm + (size_t)(bn * BN);

    const uint32_t sBase = (uint32_t)__cvta_generic_to_shared(dynsmem);

    auto load_stage = [&](int s, int kt) {
        uint32_t sA = sBase + s * STAGE_BYTES;
        uint32_t sB = sA + BM * BK * 2;
#pragma unroll
        for (int i = 0; i < 4; i++) {
            int q = tid + i * 256;
            int r = q >> 3, g = q & 7;
            const __nv_bfloat16* src = Ag + (size_t)r * DH + kt + g * 8;
            asm volatile("cp.async.cg.shared.global [%0], [%1], 16;\n"
                         :: "r"(sA + sw_off(r, g)), "l"(src));
        }
#pragma unroll
        for (int i = 0; i < 2; i++) {
            int q = tid + i * 256;
            int r = q >> 3, g = q & 7;
            const __nv_bfloat16* src = Bg + (size_t)(kt + r) * DH + g * 8;
            asm volatile("cp.async.cg.shared.global [%0], [%1], 16;\n"
                         :: "r"(sB + sw_off(r, g)), "l"(src));
        }
        asm volatile("cp.async.commit_group;\n");
    };

    float acc[2][4][4];
#pragma unroll
    for (int a = 0; a < 2; a++)
#pragma unroll
        for (int b = 0; b < 4; b++)
#pragma unroll
            for (int c = 0; c < 4; c++) acc[a][b][c] = 0.f;

    const int NKT = DH / BK;   // 8
    load_stage(0, 0);
    load_stage(1, BK);

    for (int k = 0; k < NKT; k++) {
        if (k < NKT - 1) asm volatile("cp.async.wait_group 1;\n");
        else             asm volatile("cp.async.wait_group 0;\n");
        __syncthreads();

        if (k + 2 < NKT) load_stage((k + 2) % 3, (k + 2) * BK);

        uint32_t sA = sBase + (k % 3) * STAGE_BYTES;
        uint32_t sB = sA + BM * BK * 2;
#pragma unroll
        for (int ks = 0; ks < 4; ks++) {
            uint32_t a[2][4];
#pragma unroll
            for (int mt = 0; mt < 2; mt++) {
                uint32_t row = wm * 32 + mt * 16 + (lane & 15);
                uint32_t gg  = ks * 2 + (lane >> 4);
                uint32_t addr = sA + sw_off(row, gg);
                asm volatile(
                    "ldmatrix.sync.aligned.m8n8.x4.shared.b16 {%0,%1,%2,%3}, [%4];"
                    : "=r"(a[mt][0]), "=r"(a[mt][1]), "=r"(a[mt][2]), "=r"(a[mt][3])
                    : "r"(addr));
            }
            uint32_t b[4][2];
#pragma unroll
            for (int half = 0; half < 2; half++) {
                uint32_t row = ks * 16 + (lane & 15);
                uint32_t gg  = wn * 4 + half * 2 + (lane >> 4);
                uint32_t addr = sB + sw_off(row, gg);
                uint32_t r0, r1, r2, r3;
                asm volatile(
                    "ldmatrix.sync.aligned.m8n8.x4.trans.shared.b16 {%0,%1,%2,%3}, [%4];"
                    : "=r"(r0), "=r"(r1), "=r"(r2), "=r"(r3)
                    : "r"(addr));
                b[half * 2 + 0][0] = r0; b[half * 2 + 0][1] = r1;
                b[half * 2 + 1][0] = r2; b[half * 2 + 1][1] = r3;
            }
#pragma unroll
            for (int mt = 0; mt < 2; mt++)
#pragma unroll
                for (int nt = 0; nt < 4; nt++) {
                    asm volatile(
                        "mma.sync.aligned.m16n8k16.row.col.f32.bf16.bf16.f32 "
                        "{%0,%1,%2,%3}, {%4,%5,%6,%7}, {%8,%9}, {%0,%1,%2,%3};"
                        : "+f"(acc[mt][nt][0]), "+f"(acc[mt][nt][1]),
                          "+f"(acc[mt][nt][2]), "+f"(acc[mt][nt][3])
                        : "r"(a[mt][0]), "r"(a[mt][1]), "r"(a[mt][2]), "r"(a[mt][3]),
                          "r"(b[nt][0]), "r"(b[nt][1]));
                }
        }
    }

    const int gsel = bn >> 2;
#pragma unroll
    for (int mt = 0; mt < 2; mt++) {
#pragma unroll
        for (int rr = 0; rr < 2; rr++) {
            int tok = bm * BM + wm * 32 + mt * 16 + (lane >> 2) + rr * 8;
            int grp = g_idx[tok * 2 + gsel];
            float* orow = out + (size_t)tok * DMODEL + grp * HDG;
#pragma unroll
            for (int nt = 0; nt < 4; nt++) {
                int c  = bn * BN + wn * 32 + nt * 8 + (lane & 3) * 2;
                int cl = c & (HDG - 1);
                float2 bv = *(const float2*)(bias + c);
                float2 v;
                v.x = acc[mt][nt][rr * 2 + 0] + bv.x;
                v.y = acc[mt][nt][rr * 2 + 1] + bv.y;
                *(float2*)(orow + cl) = v;
            }
        }
    }
}

// ---------------- launch ----------------
extern "C" void kernel_launch(void* const* d_in, const int* in_sizes, int n_in,
                              void* d_out, int out_size) {
    const float* x    = (const float*)d_in[0];
    const float* Wg   = (const float*)d_in[1];
    const float* Wm   = (const float*)d_in[2];
    const float* bias = (const float*)d_in[3];
    float* out = (float*)d_out;

    static bool attr_done = false;
    if (!attr_done) {
        cudaFuncSetAttribute(gate_kernel,
                             cudaFuncAttributeMaxDynamicSharedMemorySize, TOKPB * DMODEL * 4);
        cudaFuncSetAttribute(gemm_scatter,
                             cudaFuncAttributeMaxDynamicSharedMemorySize, 3 * STAGE_BYTES);
        attr_done = true;
    }

    gate_kernel<<<NTOK / TOKPB, 512, TOKPB * DMODEL * 4>>>(x, Wg, Wm, out);
    dim3 grid(DH / BN, NTOK / BM);
    gemm_scatter<<<grid, 256, 3 * STAGE_BYTES>>>(bias, out);
}

// round 11
// speedup vs baseline: 1.3036x; 1.1883x over previous
#include <cuda_runtime.h>
#include <cuda_bf16.h>
#include <cstdint>

#define NTOK 16384
#define DMODEL 2048
#define NGRP 8
#define HDG 256
#define DH 512   // k * hdg
#define TOKPB 8  // tokens per gate block

// ---------------- scratch (no allocs allowed) ----------------
__device__ __align__(16) __nv_bfloat16 g_hin[(size_t)NTOK * DH];   // 16 MB gathered, gated inputs
__device__ __align__(16) __nv_bfloat16 g_wm[(size_t)DH * DH];      // 512 KB bf16 weights ([k][n])
__device__ int g_idx[NTOK * 2];                                    // top-2 group indices per token

extern __shared__ __align__(16) unsigned char dynsmem[];

// ---------------- kernel 1 (R6 champion, verbatim): gate + passthrough + gather ------------
// 8 tokens/block, 512 threads. Thread owns ONE gate group (tid&7) and 32
// x-elements (s=tid>>3): reduce needs only 2 shuffles/warp/token.
__global__ __launch_bounds__(512, 2) void gate_kernel(const float* __restrict__ x,
                                                      const float* __restrict__ Wg,
                                                      const float* __restrict__ Wm,
                                                      float* __restrict__ out) {
    float* xs = (float*)dynsmem;                      // [TOKPB][DMODEL] fp32
    __shared__ float wsum[TOKPB][16][NGRP];
    __shared__ float sG[TOKPB][2];
    __shared__ int   sI[TOKPB][2];

    const int tid  = threadIdx.x;
    const int lane = tid & 31;
    const int warp = tid >> 5;
    const int g    = tid & 7;    // this thread's gate group
    const int s    = tid >> 3;   // element-slice index, 0..63
    const size_t tok0 = (size_t)blockIdx.x * TOKPB;

    // stage 8 token rows via cp.async in two 32KB halves (tokens 0-3, 4-7)
    const uint32_t sx = (uint32_t)__cvta_generic_to_shared(xs);
    const float* src0 = x + tok0 * DMODEL;
#pragma unroll
    for (int i = 0; i < 4; i++) {
        int q = tid + i * 512;
        asm volatile("cp.async.cg.shared.global [%0], [%1], 16;\n"
                     :: "r"(sx + q * 16), "l"(src0 + q * 4));
    }
    asm volatile("cp.async.commit_group;\n");
#pragma unroll
    for (int i = 0; i < 4; i++) {
        int q = 2048 + tid + i * 512;
        asm volatile("cp.async.cg.shared.global [%0], [%1], 16;\n"
                     :: "r"(sx + q * 16), "l"(src0 + q * 4));
    }
    asm volatile("cp.async.commit_group;\n");

    // folded Wm fp32 -> bf16 conversion (blocks 0..511 cover all of Wm)
    if (blockIdx.x < 512) {
        int i = blockIdx.x * 512 + tid;
        g_wm[i] = __float2bfloat16(Wm[i]);
    }

    // Wg column-slice register cache: Wg[e][g] for e = k*256 + s*4 + c  (32 regs)
    float wgc[32];
#pragma unroll
    for (int k = 0; k < 8; k++)
#pragma unroll
        for (int c = 0; c < 4; c++)
            wgc[k * 4 + c] = __ldg(Wg + (size_t)(k * 256 + s * 4 + c) * NGRP + g);

    // first half arrived -> logits for tokens 0-3 while 4-7 still loading
    asm volatile("cp.async.wait_group 1;\n");
    __syncthreads();

#pragma unroll 2
    for (int t = 0; t < TOKPB / 2; t++) {
        const float4* xt = (const float4*)(xs + t * DMODEL);
        float a0 = 0.f, a1 = 0.f, a2 = 0.f, a3 = 0.f;
#pragma unroll
        for (int k = 0; k < 8; k++) {
            float4 v = xt[k * 64 + s];           // broadcast across 8 same-s lanes
            a0 += v.x * wgc[k * 4 + 0];
            a1 += v.y * wgc[k * 4 + 1];
            a2 += v.z * wgc[k * 4 + 2];
            a3 += v.w * wgc[k * 4 + 3];
        }
        float p = (a0 + a1) + (a2 + a3);
        p += __shfl_xor_sync(0xffffffffu, p, 8);
        p += __shfl_xor_sync(0xffffffffu, p, 16);
        if (lane < NGRP) wsum[t][warp][lane] = p;   // lane==g for lane<8
    }

    asm volatile("cp.async.wait_group 0;\n");
    __syncthreads();

#pragma unroll 2
    for (int t = TOKPB / 2; t < TOKPB; t++) {
        const float4* xt = (const float4*)(xs + t * DMODEL);
        float a0 = 0.f, a1 = 0.f, a2 = 0.f, a3 = 0.f;
#pragma unroll
        for (int k = 0; k < 8; k++) {
            float4 v = xt[k * 64 + s];
            a0 += v.x * wgc[k * 4 + 0];
            a1 += v.y * wgc[k * 4 + 1];
            a2 += v.z * wgc[k * 4 + 2];
            a3 += v.w * wgc[k * 4 + 3];
        }
        float p = (a0 + a1) + (a2 + a3);
        p += __shfl_xor_sync(0xffffffffu, p, 8);
        p += __shfl_xor_sync(0xffffffffu, p, 16);
        if (lane < NGRP) wsum[t][warp][lane] = p;
    }
    __syncthreads();

    // softmax + top-2, one token per lane
    if (tid < TOKPB) {
        int t = tid;
        float l[NGRP];
#pragma unroll
        for (int j = 0; j < NGRP; j++) {
            float sum = 0.f;
#pragma unroll
            for (int w = 0; w < 16; w++) sum += wsum[t][w][j];
            l[j] = sum;
        }
        float m = l[0];
#pragma unroll
        for (int j = 1; j < NGRP; j++) m = fmaxf(m, l[j]);
        float e[NGRP], ssum = 0.f;
#pragma unroll
        for (int j = 0; j < NGRP; j++) { e[j] = expf(l[j] - m); ssum += e[j]; }
        int i0 = 0;
#pragma unroll
        for (int j = 1; j < NGRP; j++) if (e[j] > e[i0]) i0 = j;
        int i1 = (i0 == 0) ? 1 : 0;
#pragma unroll
        for (int j = 0; j < NGRP; j++) if (j != i0 && e[j] > e[i1]) i1 = j;
        float inv = 1.f / ssum;
        sG[t][0] = e[i0] * inv;  sG[t][1] = e[i1] * inv;
        sI[t][0] = i0;           sI[t][1] = i1;
        g_idx[(tok0 + t) * 2 + 0] = i0;
        g_idx[(tok0 + t) * 2 + 1] = i1;
    }
    __syncthreads();

    // passthrough (skip selected groups; GEMM writes those): 1 chunk/thread/token
#pragma unroll 1
    for (int t = 0; t < TOKPB; t++) {
        int i0 = sI[t][0], i1 = sI[t][1];
        int grp = tid >> 6;
        if (grp != i0 && grp != i1) {
            float4* orow = (float4*)(out + (tok0 + t) * DMODEL);
            __stcs(&orow[tid], ((const float4*)(xs + t * DMODEL))[tid]);
        }
    }
    // gather + gate -> g_hin: 2 tokens per pass, 256 threads each
#pragma unroll
    for (int it = 0; it < 4; it++) {
        int tloc = it * 2 + (tid >> 8);
        int p    = tid & 255;
        int half = p >> 7;
        float gate = sG[tloc][half];
        int base2 = sI[tloc][half] * (HDG / 2) + (p & 127);
        float2 xv = ((const float2*)(xs + tloc * DMODEL))[base2];
        ((__nv_bfloat162*)g_hin)[(tok0 + tloc) * (DH / 2) + p] =
            __floats2bfloat162_rn(gate * xv.x, gate * xv.y);
    }
}

// ---------------- kernel 2: GEMM [16384,512]x[512,512] bf16 -> fp32, scatter epilogue --------
// BM=128, BN=128, BK=64, 256 threads (8 warps: 4M x 2N, warp tile 32x64),
// 3-stage cp.async, 96KB dynamic smem, 2 blocks/SM.
#define BM 128
#define BN 128
#define BK 64
#define A_BYT (BM * BK * 2)          // 16 KB
#define B_BYT (BK * BN * 2)          // 16 KB
#define STAGE_BYTES (A_BYT + B_BYT)  // 32 KB

__device__ __forceinline__ uint32_t swA(uint32_t row, uint32_t g) {
    // A tile [128 rows x 64 bf16], 128B rows
    return row * 128u + ((g ^ (row & 7u)) * 16u);
}
__device__ __forceinline__ uint32_t swB(uint32_t row, uint32_t g) {
    // B tile [64 rows x 128 bf16], 256B rows (16 groups of 16B), XOR within 128B halves
    return row * 256u + (((g & 8u) | ((g ^ row) & 7u)) * 16u);
}

__global__ __launch_bounds__(256, 2) void gemm_scatter(const float* __restrict__ bias,
                                                       float* __restrict__ out) {
    const int tid  = threadIdx.x;
    const int lane = tid & 31;
    const int warp = tid >> 5;
    const int wm   = warp >> 1;   // 0..3 -> 32 M rows
    const int wn   = warp & 1;    // 0..1 -> 64 N cols
    const int bn   = blockIdx.x;  // 0..3
    const int bm   = blockIdx.y;  // 0..127

    const __nv_bfloat16* Ag = g_hin + (size_t)(bm * BM) * DH;
    const __nv_bfloat16* Bg = g_wm + (size_t)(bn * BN);

    const uint32_t sBase = (uint32_t)__cvta_generic_to_shared(dynsmem);

    auto load_stage = [&](int s, int kt) {
        uint32_t sA = sBase + s * STAGE_BYTES;
        uint32_t sB = sA + A_BYT;
#pragma unroll
        for (int i = 0; i < 4; i++) {         // A: 128x64 = 1024 16B chunks
            int q = tid + i * 256;
            int r = q >> 3, g = q & 7;
            const __nv_bfloat16* src = Ag + (size_t)r * DH + kt + g * 8;
            asm volatile("cp.async.cg.shared.global [%0], [%1], 16;\n"
                         :: "r"(sA + swA(r, g)), "l"(src));
        }
#pragma unroll
        for (int i = 0; i < 4; i++) {         // B: 64x128 = 1024 16B chunks
            int q = tid + i * 256;
            int r = q >> 4, g = q & 15;
            const __nv_bfloat16* src = Bg + (size_t)(kt + r) * DH + g * 8;
            asm volatile("cp.async.cg.shared.global [%0], [%1], 16;\n"
                         :: "r"(sB + swB(r, g)), "l"(src));
        }
        asm volatile("cp.async.commit_group;\n");
    };

    float acc[2][8][4];
#pragma unroll
    for (int a = 0; a < 2; a++)
#pragma unroll
        for (int b = 0; b < 8; b++)
#pragma unroll
            for (int c = 0; c < 4; c++) acc[a][b][c] = 0.f;

    const int NKT = DH / BK;   // 8
    load_stage(0, 0);
    load_stage(1, BK);

    for (int k = 0; k < NKT; k++) {
        if (k < NKT - 1) asm volatile("cp.async.wait_group 1;\n");
        else             asm volatile("cp.async.wait_group 0;\n");
        __syncthreads();

        if (k + 2 < NKT) load_stage((k + 2) % 3, (k + 2) * BK);

        uint32_t sA = sBase + (k % 3) * STAGE_BYTES;
        uint32_t sB = sA + A_BYT;
#pragma unroll
        for (int ks = 0; ks < 4; ks++) {
            uint32_t a[2][4];
#pragma unroll
            for (int mt = 0; mt < 2; mt++) {
                uint32_t row = wm * 32 + mt * 16 + (lane & 15);
                uint32_t gg  = ks * 2 + (lane >> 4);
                uint32_t addr = sA + swA(row, gg);
                asm volatile(
                    "ldmatrix.sync.aligned.m8n8.x4.shared.b16 {%0,%1,%2,%3}, [%4];"
                    : "=r"(a[mt][0]), "=r"(a[mt][1]), "=r"(a[mt][2]), "=r"(a[mt][3])
                    : "r"(addr));
            }
            uint32_t b[8][2];
#pragma unroll
            for (int q4 = 0; q4 < 4; q4++) {
                uint32_t row = ks * 16 + (lane & 15);
                uint32_t gg  = wn * 8 + q4 * 2 + (lane >> 4);
                uint32_t addr = sB + swB(row, gg);
                uint32_t r0, r1, r2, r3;
                asm volatile(
                    "ldmatrix.sync.aligned.m8n8.x4.trans.shared.b16 {%0,%1,%2,%3}, [%4];"
                    : "=r"(r0), "=r"(r1), "=r"(r2), "=r"(r3)
                    : "r"(addr));
                b[q4 * 2 + 0][0] = r0; b[q4 * 2 + 0][1] = r1;
                b[q4 * 2 + 1][0] = r2; b[q4 * 2 + 1][1] = r3;
            }
#pragma unroll
            for (int mt = 0; mt < 2; mt++)
#pragma unroll
                for (int nt = 0; nt < 8; nt++) {
                    asm volatile(
                        "mma.sync.aligned.m16n8k16.row.col.f32.bf16.bf16.f32 "
                        "{%0,%1,%2,%3}, {%4,%5,%6,%7}, {%8,%9}, {%0,%1,%2,%3};"
                        : "+f"(acc[mt][nt][0]), "+f"(acc[mt][nt][1]),
                          "+f"(acc[mt][nt][2]), "+f"(acc[mt][nt][3])
                        : "r"(a[mt][0]), "r"(a[mt][1]), "r"(a[mt][2]), "r"(a[mt][3]),
                          "r"(b[nt][0]), "r"(b[nt][1]));
                }
        }
    }

    // epilogue: add bias, scatter into out at selected group.
    const int gsel = bn >> 1;   // (bn*128)/256: which selected slot (block-constant)
#pragma unroll
    for (int mt = 0; mt < 2; mt++) {
#pragma unroll
        for (int rr = 0; rr < 2; rr++) {
            int tok = bm * BM + wm * 32 + mt * 16 + (lane >> 2) + rr * 8;
            int grp = g_idx[tok * 2 + gsel];
            float* orow = out + (size_t)tok * DMODEL + grp * HDG;
#pragma unroll
            for (int nt = 0; nt < 8; nt++) {
                int c  = bn * BN + wn * 64 + nt * 8 + (lane & 3) * 2;
                int cl = c & (HDG - 1);
                float2 bv = *(const float2*)(bias + c);
                float2 v;
                v.x = acc[mt][nt][rr * 2 + 0] + bv.x;
                v.y = acc[mt][nt][rr * 2 + 1] + bv.y;
                *(float2*)(orow + cl) = v;
            }
        }
    }
}

// ---------------- launch ----------------
extern "C" void kernel_launch(void* const* d_in, const int* in_sizes, int n_in,
                              void* d_out, int out_size) {
    const float* x    = (const float*)d_in[0];
    const float* Wg   = (const float*)d_in[1];
    const float* Wm   = (const float*)d_in[2];
    const float* bias = (const float*)d_in[3];
    float* out = (float*)d_out;

    static bool attr_done = false;
    if (!attr_done) {
        cudaFuncSetAttribute(gate_kernel,
                             cudaFuncAttributeMaxDynamicSharedMemorySize, TOKPB * DMODEL * 4);
        cudaFuncSetAttribute(gemm_scatter,
                             cudaFuncAttributeMaxDynamicSharedMemorySize, 3 * STAGE_BYTES);
        attr_done = true;
    }

    gate_kernel<<<NTOK / TOKPB, 512, TOKPB * DMODEL * 4>>>(x, Wg, Wm, out);
    dim3 grid(DH / BN, NTOK / BM);
    gemm_scatter<<<grid, 256, 3 * STAGE_BYTES>>>(bias, out);
}